// round 9
// baseline (speedup 1.0000x reference)
#include <cuda_runtime.h>
#include <cuda_fp16.h>
#include <cstdint>

#define NN 4096
#define II 512
#define HH 2048
#define OO 512
#define NG 8        // groups of 64 input / 64 output cols
#define NHC 8       // h chunks of 256
#define HCW 256
#define NSP 16      // output splits = NHC * 2 (wn pairs)

// device scratch
__device__ __half d_xh[(size_t)NN * II];
__device__ __half d_W1h[(size_t)II * HH];
__device__ __half d_W2h[(size_t)HH * OO];
__device__ __half d_Ph[(size_t)NSP * NN * OO];   // split-K partials [s][n][o], fp16

// ---------------- helpers ----------------
__device__ __forceinline__ void mma_f16(float c[4],
                                        uint32_t a0, uint32_t a1, uint32_t a2, uint32_t a3,
                                        uint32_t b0, uint32_t b1) {
    asm volatile(
        "mma.sync.aligned.m16n8k16.row.col.f32.f16.f16.f32 "
        "{%0,%1,%2,%3}, {%4,%5,%6,%7}, {%8,%9}, {%0,%1,%2,%3};"
        : "+f"(c[0]), "+f"(c[1]), "+f"(c[2]), "+f"(c[3])
        : "r"(a0), "r"(a1), "r"(a2), "r"(a3), "r"(b0), "r"(b1));
}
__device__ __forceinline__ void ldsm4(uint32_t& r0, uint32_t& r1, uint32_t& r2, uint32_t& r3,
                                      uint32_t addr) {
    asm volatile("ldmatrix.sync.aligned.m8n8.x4.shared.b16 {%0,%1,%2,%3}, [%4];"
                 : "=r"(r0), "=r"(r1), "=r"(r2), "=r"(r3) : "r"(addr));
}
__device__ __forceinline__ void ldsm4t(uint32_t& r0, uint32_t& r1, uint32_t& r2, uint32_t& r3,
                                       uint32_t addr) {
    asm volatile("ldmatrix.sync.aligned.m8n8.x4.trans.shared.b16 {%0,%1,%2,%3}, [%4];"
                 : "=r"(r0), "=r"(r1), "=r"(r2), "=r"(r3) : "r"(addr));
}
__device__ __forceinline__ uint32_t smem_u32(const void* p) {
    uint32_t a;
    asm("{ .reg .u64 t; cvta.to.shared.u64 t, %1; cvt.u32.u64 %0, t; }" : "=r"(a) : "l"(p));
    return a;
}
__device__ __forceinline__ uint32_t pack_h2(float a, float b) {
    __half2 h = __floats2half2_rn(a, b);
    return *reinterpret_cast<uint32_t*>(&h);
}
#define CP16(dst, src) \
    asm volatile("cp.async.cg.shared.global [%0], [%1], 16;" :: "r"(dst), "l"(src) : "memory")
#define CP_COMMIT() asm volatile("cp.async.commit_group;" ::: "memory")
#define CP_WAIT0()  asm volatile("cp.async.wait_group 0;" ::: "memory")
#define BAR_HALF(id) asm volatile("bar.sync %0, 128;" :: "r"(id) : "memory")

// ---------------- f32 -> f16 prep (single launch) ----------------
#define CX  (NN * II / 4)          // 524288 float4 chunks
#define CW1 (II * HH / 4)          // 262144
#define CW2 (HH * OO / 4)          // 262144
__global__ __launch_bounds__(256) void conv_all(const float* __restrict__ x,
                                                const float* __restrict__ W1,
                                                const float* __restrict__ W2) {
    size_t i = (size_t)blockIdx.x * 256 + threadIdx.x;
    const float* s; uint2* d; size_t j;
    if (i < CX)            { s = x;  d = (uint2*)d_xh;  j = i; }
    else if (i < CX + CW1) { s = W1; d = (uint2*)d_W1h; j = i - CX; }
    else                   { s = W2; d = (uint2*)d_W2h; j = i - CX - CW1; }
    float4 v = ((const float4*)s)[j];
    d[j] = make_uint2(pack_h2(v.x, v.y), pack_h2(v.z, v.w));
}

// ---------------- smem layout ----------------
// x  tile [m=64 ][k=64 ] pitch 72 halves (144B rows; ldmatrix conflict-free)
// W1 tile [k=64 ][n=256] pitch 264 (528B)
// W2 tile [k=256][n=64 ] pitch 72
// exchange regions: 8 x [32m][32o] half, pitch 40 halves (80B) -> banks 4*gq+tq, conflict-free
#define PA   72
#define PW1  264
#define PW2  72
#define PRG  40
#define RGB  2560                       // 32*80 bytes per region
#define HB_X   0
#define HB_W1  9216                     // 64*144
#define HB_W2  43008                    // + 64*528
#define HB_R   79872                    // + 256*144
#define HB_B1  (HB_R + 8 * RGB)         // 100352
#define SM_TOTAL (HB_B1 + HCW * 4)      // 101376 -> 2 CTAs/SM

__device__ __forceinline__ void stage_all(uint32_t sb, int tid, int rm, int g, int hc) {
    #pragma unroll
    for (int i = 0; i < 2; i++) {                     // x: 64x64 h
        int t = tid + i * 256;
        int r = t >> 3, c = t & 7;
        CP16(sb + HB_X + r * 144 + c * 16,
             d_xh + (size_t)(rm * 64 + r) * II + g * 64 + c * 8);
    }
    #pragma unroll
    for (int i = 0; i < 8; i++) {                     // W1: 64x256 h
        int t = tid + i * 256;
        int k = t >> 5, c = t & 31;
        CP16(sb + HB_W1 + k * 528 + c * 16,
             d_W1h + (size_t)(g * 64 + k) * HH + hc * HCW + c * 8);
    }
    #pragma unroll
    for (int i = 0; i < 8; i++) {                     // W2: 256x64 h
        int t = tid + i * 256;
        int k = t >> 3, c = t & 7;
        CP16(sb + HB_W2 + k * 144 + c * 16,
             d_W2h + (size_t)(hc * HCW + k) * OO + g * 64 + c * 8);
    }
    CP_COMMIT();
}

// MMA2 over one n32 chunk, A-fragments built from zacc registers (bias+relu on the fly)
__device__ __forceinline__ void mma2_chunk(float oacc[2][4][4], const float zacc[2][8][4],
                                           const float* b1s, uint32_t sb, int chunk,
                                           int wn, int lrow, int lk8, int tq) {
    #pragma unroll
    for (int mi = 0; mi < 2; mi++)
        #pragma unroll
        for (int nt = 0; nt < 4; nt++)
            #pragma unroll
            for (int j = 0; j < 4; j++)
                oacc[mi][nt][j] = 0.0f;

    #pragma unroll
    for (int kb = 0; kb < 4; kb++) {
        const int c0 = wn * 64 + kb * 16 + 2 * tq;
        const float ba0 = b1s[c0],     ba1 = b1s[c0 + 1];
        const float bb0 = b1s[c0 + 8], bb1 = b1s[c0 + 9];
        uint32_t af[2][4];
        #pragma unroll
        for (int mi = 0; mi < 2; mi++) {
            af[mi][0] = pack_h2(fmaxf(zacc[mi][2*kb][0] + ba0, 0.f),
                                fmaxf(zacc[mi][2*kb][1] + ba1, 0.f));
            af[mi][1] = pack_h2(fmaxf(zacc[mi][2*kb][2] + ba0, 0.f),
                                fmaxf(zacc[mi][2*kb][3] + ba1, 0.f));
            af[mi][2] = pack_h2(fmaxf(zacc[mi][2*kb+1][0] + bb0, 0.f),
                                fmaxf(zacc[mi][2*kb+1][1] + bb1, 0.f));
            af[mi][3] = pack_h2(fmaxf(zacc[mi][2*kb+1][2] + bb0, 0.f),
                                fmaxf(zacc[mi][2*kb+1][3] + bb1, 0.f));
        }
        const int kk = wn * 64 + kb * 16 + lrow;
        #pragma unroll
        for (int ntp = 0; ntp < 2; ntp++) {
            const int nn = chunk * 32 + ntp * 16 + lk8;
            uint32_t b0, b1r, b2, b3;
            ldsm4t(b0, b1r, b2, b3, sb + HB_W2 + (uint32_t)(kk * PW2 + nn) * 2);
            #pragma unroll
            for (int mi = 0; mi < 2; mi++) {
                mma_f16(oacc[mi][ntp*2],   af[mi][0], af[mi][1], af[mi][2], af[mi][3], b0, b1r);
                mma_f16(oacc[mi][ntp*2+1], af[mi][0], af[mi][1], af[mi][2], af[mi][3], b2, b3);
            }
        }
    }
}

__global__ __launch_bounds__(256, 2) void fused_kernel(const float* __restrict__ b1)
{
    extern __shared__ char smraw[];
    float* b1s = reinterpret_cast<float*>(smraw + HB_B1);
    const uint32_t sb = smem_u32(smraw);

    const int tid  = threadIdx.x;
    const int wid  = tid >> 5;
    const int lane = tid & 31;
    const int gq   = lane >> 2;
    const int tq   = lane & 3;
    const int wm   = wid >> 2;      // 0..1 : 32 M-rows (tids 0-127 / 128-255)
    const int wn   = wid & 3;       // 0..3 : 64-wide H slice
    const int hc   = blockIdx.x;    // 0..7
    const int rm   = blockIdx.y;    // 0..63

    const int lrow = (lane & 7) + ((lane >> 3) & 1) * 8;
    const int lk8  = (lane >> 4) << 3;

    if (tid < 64) {
        float4 v = *(const float4*)(b1 + hc * HCW + tid * 4);
        *(float4*)(b1s + tid * 4) = v;
    }

    // Z accumulators persist across all 8 groups: warp tile 32(m) x 64(h)
    float zacc[2][8][4];
    #pragma unroll
    for (int mi = 0; mi < 2; mi++)
        #pragma unroll
        for (int ni = 0; ni < 8; ni++)
            #pragma unroll
            for (int j = 0; j < 4; j++)
                zacc[mi][ni][j] = 0.0f;

    stage_all(sb, tid, rm, 0, hc);

    for (int g = 0; g < NG; g++) {
        CP_WAIT0();
        __syncthreads();

        // ---- MMA1: Z += x_g @ W1_g  (warp 32x64, K=64) ----
        #pragma unroll
        for (int ks = 0; ks < 4; ks++) {
            const int k0 = ks * 16;
            uint32_t a[2][4];
            #pragma unroll
            for (int mi = 0; mi < 2; mi++)
                ldsm4(a[mi][0], a[mi][1], a[mi][2], a[mi][3],
                      sb + HB_X + (uint32_t)((wm * 32 + mi * 16 + lrow) * PA + k0 + lk8) * 2);
            #pragma unroll
            for (int np = 0; np < 4; np++) {
                int kk = k0 + lrow;
                int nn = wn * 64 + np * 16 + lk8;
                uint32_t b0, b1r, b2, b3;
                ldsm4t(b0, b1r, b2, b3, sb + HB_W1 + (uint32_t)(kk * PW1 + nn) * 2);
                #pragma unroll
                for (int mi = 0; mi < 2; mi++) {
                    mma_f16(zacc[mi][np * 2],     a[mi][0], a[mi][1], a[mi][2], a[mi][3], b0, b1r);
                    mma_f16(zacc[mi][np * 2 + 1], a[mi][0], a[mi][1], a[mi][2], a[mi][3], b2, b3);
                }
            }
        }

        float oacc[2][4][4];

        // ================= chunk 0 (O-cols 0..31 of group) =================
        mma2_chunk(oacc, zacc, b1s, sb, 0, wn, lrow, lk8, tq);

        if (wn >= 2) {   // store partial to exchange region A
            const uint32_t rb = sb + HB_R + (uint32_t)((wm * 2 + wn - 2)) * RGB;
            #pragma unroll
            for (int mi = 0; mi < 2; mi++)
                #pragma unroll
                for (int nt = 0; nt < 4; nt++) {
                    uint32_t ad = rb + (uint32_t)((mi * 16 + gq) * 80 + (nt * 8 + 2 * tq) * 2);
                    asm volatile("st.shared.b32 [%0], %1;" :: "r"(ad),
                                 "r"(pack_h2(oacc[mi][nt][0], oacc[mi][nt][1])) : "memory");
                    asm volatile("st.shared.b32 [%0], %1;" :: "r"(ad + 8 * 80),
                                 "r"(pack_h2(oacc[mi][nt][2], oacc[mi][nt][3])) : "memory");
                }
        }
        BAR_HALF(1 + wm);

        if (wn < 2) {    // add partner partial, write split g-chunk0 to gmem
            const uint32_t rb = sb + HB_R + (uint32_t)(wm * 2 + wn) * RGB;
            const int s = hc * 2 + wn;
            #pragma unroll
            for (int mi = 0; mi < 2; mi++) {
                const size_t n0 = (size_t)rm * 64 + wm * 32 + mi * 16 + gq;
                __half* p0 = d_Ph + ((size_t)s * NN + n0) * OO + g * 64;
                #pragma unroll
                for (int nt = 0; nt < 4; nt++) {
                    uint32_t ad = rb + (uint32_t)((mi * 16 + gq) * 80 + (nt * 8 + 2 * tq) * 2);
                    uint32_t u0, u1;
                    asm volatile("ld.shared.b32 %0, [%1];" : "=r"(u0) : "r"(ad));
                    asm volatile("ld.shared.b32 %0, [%1];" : "=r"(u1) : "r"(ad + 8 * 80));
                    float2 f0 = __half22float2(*reinterpret_cast<__half2*>(&u0));
                    float2 f1 = __half22float2(*reinterpret_cast<__half2*>(&u1));
                    const int c = nt * 8 + 2 * tq;
                    *(uint32_t*)(p0 + c) =
                        pack_h2(oacc[mi][nt][0] + f0.x, oacc[mi][nt][1] + f0.y);
                    *(uint32_t*)(p0 + 8 * OO + c) =
                        pack_h2(oacc[mi][nt][2] + f1.x, oacc[mi][nt][3] + f1.y);
                }
            }
        }

        // ================= chunk 1 (O-cols 32..63 of group) =================
        mma2_chunk(oacc, zacc, b1s, sb, 1, wn, lrow, lk8, tq);

        if (wn >= 2) {   // store partial to exchange region B
            const uint32_t rb = sb + HB_R + (uint32_t)(4 + wm * 2 + wn - 2) * RGB;
            #pragma unroll
            for (int mi = 0; mi < 2; mi++)
                #pragma unroll
                for (int nt = 0; nt < 4; nt++) {
                    uint32_t ad = rb + (uint32_t)((mi * 16 + gq) * 80 + (nt * 8 + 2 * tq) * 2);
                    asm volatile("st.shared.b32 [%0], %1;" :: "r"(ad),
                                 "r"(pack_h2(oacc[mi][nt][0], oacc[mi][nt][1])) : "memory");
                    asm volatile("st.shared.b32 [%0], %1;" :: "r"(ad + 8 * 80),
                                 "r"(pack_h2(oacc[mi][nt][2], oacc[mi][nt][3])) : "memory");
                }
        }
        __syncthreads();   // orders region-B stores; all tile reads done -> restage

        if (g < NG - 1) stage_all(sb, tid, rm, g + 1, hc);

        if (wn < 2) {    // add partner partial, write split g-chunk1 to gmem
            const uint32_t rb = sb + HB_R + (uint32_t)(4 + wm * 2 + wn) * RGB;
            const int s = hc * 2 + wn;
            #pragma unroll
            for (int mi = 0; mi < 2; mi++) {
                const size_t n0 = (size_t)rm * 64 + wm * 32 + mi * 16 + gq;
                __half* p0 = d_Ph + ((size_t)s * NN + n0) * OO + g * 64 + 32;
                #pragma unroll
                for (int nt = 0; nt < 4; nt++) {
                    uint32_t ad = rb + (uint32_t)((mi * 16 + gq) * 80 + (nt * 8 + 2 * tq) * 2);
                    uint32_t u0, u1;
                    asm volatile("ld.shared.b32 %0, [%1];" : "=r"(u0) : "r"(ad));
                    asm volatile("ld.shared.b32 %0, [%1];" : "=r"(u1) : "r"(ad + 8 * 80));
                    float2 f0 = __half22float2(*reinterpret_cast<__half2*>(&u0));
                    float2 f1 = __half22float2(*reinterpret_cast<__half2*>(&u1));
                    const int c = nt * 8 + 2 * tq;
                    *(uint32_t*)(p0 + c) =
                        pack_h2(oacc[mi][nt][0] + f0.x, oacc[mi][nt][1] + f0.y);
                    *(uint32_t*)(p0 + 8 * OO + c) =
                        pack_h2(oacc[mi][nt][2] + f1.x, oacc[mi][nt][3] + f1.y);
                }
            }
        }
    }
}

// out[n][o] = b2[o] + sum_s d_Ph[s][n][o]
__global__ __launch_bounds__(256) void reduce_kernel(const float* __restrict__ b2,
                                                     float* __restrict__ out)
{
    const size_t idx = (size_t)blockIdx.x * 256 + threadIdx.x;   // 4-elem chunk index
    const int oq = (int)(idx & (OO / 4 - 1)) * 4;
    float4 acc = *(const float4*)(b2 + oq);
    #pragma unroll
    for (int s = 0; s < NSP; s++) {
        uint2 pv = *(const uint2*)((const __half*)d_Ph + (size_t)s * NN * OO + idx * 4);
        float2 lo = __half22float2(*reinterpret_cast<__half2*>(&pv.x));
        float2 hi = __half22float2(*reinterpret_cast<__half2*>(&pv.y));
        acc.x += lo.x; acc.y += lo.y; acc.z += hi.x; acc.w += hi.y;
    }
    *(float4*)(out + idx * 4) = acc;
}

extern "C" void kernel_launch(void* const* d_in, const int* in_sizes, int n_in,
                              void* d_out, int out_size)
{
    const float* x  = (const float*)d_in[0];
    const float* W1 = (const float*)d_in[1];
    const float* b1 = (const float*)d_in[2];
    const float* W2 = (const float*)d_in[3];
    const float* b2 = (const float*)d_in[4];
    float* out = (float*)d_out;

    cudaFuncSetAttribute(fused_kernel, cudaFuncAttributeMaxDynamicSharedMemorySize, SM_TOTAL);

    conv_all<<<(CX + CW1 + CW2) / 256, 256>>>(x, W1, W2);
    fused_kernel<<<dim3(NHC, NN / 64), 256, SM_TOTAL>>>(b1);
    reduce_kernel<<<(NN * OO / 4) / 256, 256>>>(b2, out);
}